// round 6
// baseline (speedup 1.0000x reference)
#include <cuda_runtime.h>
#include <math.h>

#define NPIX (256*256)
#define BATCH 8
#define QKV_CH 192
#define GRAM_STRIDE 1088   // 32*32 Gqk + 32 qn2 + 32 kn2

typedef unsigned long long ull;

// Scratch (device globals — no allocation allowed). All fp32: the top-k
// selection is an order-statistic discontinuity; quantizing q/k flips
// selections and fails the 1e-3 gate (measured round 4: 1.1e-2).
__device__ float g_qkv  [(size_t)BATCH * QKV_CH * NPIX];
__device__ float g_qkvdw[(size_t)BATCH * QKV_CH * NPIX];
__device__ float g_gram [BATCH * 2 * GRAM_STRIDE];
__device__ float g_M    [BATCH * 64 * 64];

// ---------------------------------------------------------------------------
// f32x2 packed-FMA helpers (rn rounding == fmaf bit-exact per lane)
// ---------------------------------------------------------------------------
__device__ __forceinline__ ull pack2(float lo, float hi) {
    ull r; asm("mov.b64 %0, {%1, %2};" : "=l"(r) : "f"(lo), "f"(hi)); return r;
}
__device__ __forceinline__ ull ffma2(ull a, ull b, ull c) {
    ull d; asm("fma.rn.f32x2 %0, %1, %2, %3;" : "=l"(d) : "l"(a), "l"(b), "l"(c)); return d;
}
__device__ __forceinline__ float2 unpack2(ull v) {
    float2 f; asm("mov.b64 {%0, %1}, %2;" : "=f"(f.x), "=f"(f.y) : "l"(v)); return f;
}

// ---------------------------------------------------------------------------
// K0: zero gram accumulators (norms come from K2, gram from K3)
// ---------------------------------------------------------------------------
__global__ void k0_zero() {
    int i = blockIdx.x * 256 + threadIdx.x;
    if (i < BATCH * 2 * GRAM_STRIDE) g_gram[i] = 0.f;
}

// ---------------------------------------------------------------------------
// K1: qkv 1x1 conv == per-batch GEMM [192,64]x[64,N], FFMA2 micro-tile.
// block 256 thr: 64 out-ch x 128 px; thread: 8 o (4 packed pairs) x 4 px
// ---------------------------------------------------------------------------
__global__ __launch_bounds__(256) void k1_qkv(const float* __restrict__ x,
                                              const float* __restrict__ wqkv) {
    __shared__ float xs[64][128];
    __shared__ float ws[64][64];
    int b  = blockIdx.z;
    int o0 = blockIdx.y * 64;
    int p0 = blockIdx.x * 128;

    const float* xb = x + (size_t)b * 64 * NPIX;
    for (int i = threadIdx.x; i < 64 * 32; i += 256) {
        int c = i >> 5, s = i & 31;
        *(float4*)&xs[c][s * 4] = *(const float4*)&xb[(size_t)c * NPIX + p0 + s * 4];
    }
    for (int i = threadIdx.x; i < 64 * 64; i += 256) {
        int c = i & 63, orow = i >> 6;
        ws[c][orow] = wqkv[(o0 + orow) * 64 + c];
    }
    __syncthreads();

    int og = threadIdx.x >> 5, pg = threadIdx.x & 31;
    int ol0 = og * 8, pl0 = pg * 4;

    ull acc2[4][4];
#pragma unroll
    for (int o = 0; o < 4; o++)
#pragma unroll
        for (int p = 0; p < 4; p++) acc2[o][p] = 0ull;

#pragma unroll 8
    for (int c = 0; c < 64; c++) {
        ulonglong2 w01 = *(const ulonglong2*)&ws[c][ol0];
        ulonglong2 w23 = *(const ulonglong2*)&ws[c][ol0 + 4];
        float4 xv = *(const float4*)&xs[c][pl0];
        ull wp[4] = {w01.x, w01.y, w23.x, w23.y};
        ull xd[4] = {pack2(xv.x, xv.x), pack2(xv.y, xv.y),
                     pack2(xv.z, xv.z), pack2(xv.w, xv.w)};
#pragma unroll
        for (int o = 0; o < 4; o++)
#pragma unroll
            for (int p = 0; p < 4; p++)
                acc2[o][p] = ffma2(wp[o], xd[p], acc2[o][p]);
    }

    float* outb = g_qkv + (size_t)b * QKV_CH * NPIX;
#pragma unroll
    for (int o = 0; o < 4; o++) {
        float2 u0 = unpack2(acc2[o][0]);
        float2 u1 = unpack2(acc2[o][1]);
        float2 u2 = unpack2(acc2[o][2]);
        float2 u3 = unpack2(acc2[o][3]);
        float4 rA = make_float4(u0.x, u1.x, u2.x, u3.x);
        float4 rB = make_float4(u0.y, u1.y, u2.y, u3.y);
        *(float4*)&outb[(size_t)(o0 + ol0 + 2 * o    ) * NPIX + p0 + pl0] = rA;
        *(float4*)&outb[(size_t)(o0 + ol0 + 2 * o + 1) * NPIX + p0 + pl0] = rB;
    }
}

// ---------------------------------------------------------------------------
// K2: depthwise 3x3, pad 1. 16 output rows/block, sliding 3-row register
// window. For ch<128 (q,k) also accumulate per-channel L2 norms into g_gram.
// ---------------------------------------------------------------------------
__global__ __launch_bounds__(256) void k2_dw(const float* __restrict__ wdw) {
    int b = blockIdx.z, ch = blockIdx.y, r0 = blockIdx.x * 16;
    __shared__ float rows[18][256];
    int tid = threadIdx.x;

    const float* in = g_qkv + ((size_t)(b * QKV_CH + ch)) * NPIX;
    for (int i = tid; i < 18 * 64; i += 256) {
        int row = i >> 6, seg = i & 63;
        int gr = r0 - 1 + row;
        float4 v = (gr >= 0 && gr < 256)
                 ? *(const float4*)(in + gr * 256 + seg * 4)
                 : make_float4(0.f, 0.f, 0.f, 0.f);
        *(float4*)&rows[row][seg * 4] = v;
    }
    __syncthreads();

    float w[9];
#pragma unroll
    for (int i = 0; i < 9; i++) w[i] = wdw[ch * 9 + i];

    int tx = tid;
    bool hasL = tx > 0, hasR = tx < 255;

    float vals[16];
    float l0, m0, r0v, l1, m1, r1v, l2, m2, r2v;
    m0 = rows[0][tx]; l0 = hasL ? rows[0][tx - 1] : 0.f; r0v = hasR ? rows[0][tx + 1] : 0.f;
    m1 = rows[1][tx]; l1 = hasL ? rows[1][tx - 1] : 0.f; r1v = hasR ? rows[1][tx + 1] : 0.f;
#pragma unroll
    for (int rr = 0; rr < 16; rr++) {
        m2 = rows[rr + 2][tx];
        l2 = hasL ? rows[rr + 2][tx - 1] : 0.f;
        r2v = hasR ? rows[rr + 2][tx + 1] : 0.f;
        float acc = 0.f;
        acc = fmaf(w[0], l0, acc); acc = fmaf(w[1], m0, acc); acc = fmaf(w[2], r0v, acc);
        acc = fmaf(w[3], l1, acc); acc = fmaf(w[4], m1, acc); acc = fmaf(w[5], r1v, acc);
        acc = fmaf(w[6], l2, acc); acc = fmaf(w[7], m2, acc); acc = fmaf(w[8], r2v, acc);
        vals[rr] = acc;
        l0 = l1; m0 = m1; r0v = r1v;
        l1 = l2; m1 = m2; r1v = r2v;
    }

    float* out = g_qkvdw + ((size_t)(b * QKV_CH + ch)) * NPIX;
#pragma unroll
    for (int rr = 0; rr < 16; rr++)
        out[(r0 + rr) * 256 + tx] = vals[rr];

    if (ch < 128) {
        float ss = 0.f;
#pragma unroll
        for (int rr = 0; rr < 16; rr++) ss = fmaf(vals[rr], vals[rr], ss);
#pragma unroll
        for (int o = 16; o; o >>= 1) ss += __shfl_xor_sync(0xffffffffu, ss, o);
        if ((tx & 31) == 0) {
            int h = (ch >> 5) & 1, c = ch & 31;
            float* gg = g_gram + ((size_t)(b * 2 + h)) * GRAM_STRIDE;
            atomicAdd(&gg[(ch < 64 ? 1024 : 1056) + c], ss);
        }
    }
}

// ---------------------------------------------------------------------------
// K3: Gram only (norms in K2). grid (64,2,8) = 1024 blocks for occupancy.
// 256 thr = 4 groups x 64 thr; group covers 256 px; thread = 4x4 tile, FFMA2.
// ---------------------------------------------------------------------------
__global__ __launch_bounds__(256) void k3_gram() {
    int b = blockIdx.z, h = blockIdx.y, chunk = blockIdx.x;
    int g = threadIdx.x >> 6, t = threadIdx.x & 63;
    int tc = t >> 3, td = t & 7;
    __shared__ float qs[4][32][36];            // [group][px][ch]
    __shared__ float ks[4][32][36];
    size_t qbase = ((size_t)b * QKV_CH +      h * 32) * NPIX + chunk * 1024 + g * 256;
    size_t kbase = ((size_t)b * QKV_CH + 64 + h * 32) * NPIX + chunk * 1024 + g * 256;

    ull acc2[4][2];
#pragma unroll
    for (int i = 0; i < 4; i++) { acc2[i][0] = 0ull; acc2[i][1] = 0ull; }

    for (int s = 0; s < 256; s += 32) {
        __syncthreads();
#pragma unroll
        for (int r = 0; r < 4; r++) {
            int i = t + r * 64;                // 0..255 slots
            int ch = i >> 3, p4 = i & 7;       // 32 ch x 8 float4 (32 px)
            float4 qv = *(const float4*)&g_qkvdw[qbase + (size_t)ch * NPIX + s + p4 * 4];
            float4 kv = *(const float4*)&g_qkvdw[kbase + (size_t)ch * NPIX + s + p4 * 4];
            qs[g][p4 * 4 + 0][ch] = qv.x; qs[g][p4 * 4 + 1][ch] = qv.y;
            qs[g][p4 * 4 + 2][ch] = qv.z; qs[g][p4 * 4 + 3][ch] = qv.w;
            ks[g][p4 * 4 + 0][ch] = kv.x; ks[g][p4 * 4 + 1][ch] = kv.y;
            ks[g][p4 * 4 + 2][ch] = kv.z; ks[g][p4 * 4 + 3][ch] = kv.w;
        }
        __syncthreads();
#pragma unroll 4
        for (int p = 0; p < 32; p++) {
            float4 q4 = *(const float4*)&qs[g][p][tc * 4];
            ulonglong2 kp = *(const ulonglong2*)&ks[g][p][td * 4];
            ull qd;
            qd = pack2(q4.x, q4.x);
            acc2[0][0] = ffma2(qd, kp.x, acc2[0][0]);
            acc2[0][1] = ffma2(qd, kp.y, acc2[0][1]);
            qd = pack2(q4.y, q4.y);
            acc2[1][0] = ffma2(qd, kp.x, acc2[1][0]);
            acc2[1][1] = ffma2(qd, kp.y, acc2[1][1]);
            qd = pack2(q4.z, q4.z);
            acc2[2][0] = ffma2(qd, kp.x, acc2[2][0]);
            acc2[2][1] = ffma2(qd, kp.y, acc2[2][1]);
            qd = pack2(q4.w, q4.w);
            acc2[3][0] = ffma2(qd, kp.x, acc2[3][0]);
            acc2[3][1] = ffma2(qd, kp.y, acc2[3][1]);
        }
    }

    float* gg = g_gram + ((size_t)(b * 2 + h)) * GRAM_STRIDE;
#pragma unroll
    for (int i = 0; i < 4; i++) {
        int c = tc * 4 + i;
#pragma unroll
        for (int jp = 0; jp < 2; jp++) {
            float2 v = unpack2(acc2[i][jp]);
            atomicAdd(&gg[c * 32 + td * 4 + jp * 2 + 0], v.x);
            atomicAdd(&gg[c * 32 + td * 4 + jp * 2 + 1], v.y);
        }
    }
}

// ---------------------------------------------------------------------------
// K4: normalize attn, triple top-k softmax, fold Wproj -> M[64][64]
// ---------------------------------------------------------------------------
__device__ __forceinline__ float warp_sort_desc(float v, int lane) {
#pragma unroll
    for (int k = 2; k <= 32; k <<= 1) {
#pragma unroll
        for (int j = k >> 1; j > 0; j >>= 1) {
            float o = __shfl_xor_sync(0xffffffffu, v, j);
            bool up  = ((lane & k) == 0);
            bool low = ((lane & j) == 0);
            float mx = fmaxf(v, o), mn = fminf(v, o);
            v = (up == low) ? mx : mn;
        }
    }
    return v;
}

__device__ __forceinline__ float topk_weight(float orig, float thr, int kk,
                                             int lane, float rowmax) {
    unsigned full = 0xffffffffu;
    unsigned gt = __ballot_sync(full, orig > thr);
    int need = kk - __popc(gt);
    unsigned eq = __ballot_sync(full, orig == thr);
    unsigned lt_mask = (1u << lane) - 1u;
    bool incl = (orig > thr) ||
                ((orig == thr) && ((int)__popc(eq & lt_mask) < need));
    float e = incl ? expf(orig - rowmax) : 0.f;
    float s = e;
#pragma unroll
    for (int o = 16; o; o >>= 1) s += __shfl_xor_sync(full, s, o);
    return e / s;
}

__global__ __launch_bounds__(1024) void k4_combine(const float* __restrict__ wproj,
                                                   const float* __restrict__ temperature,
                                                   const float* __restrict__ a1p,
                                                   const float* __restrict__ a2p,
                                                   const float* __restrict__ a3p) {
    int b = blockIdx.x;
    int wid = threadIdx.x >> 5, lane = threadIdx.x & 31;
    __shared__ float A_s[2][32][32];
    float a1 = a1p[0], a2 = a2p[0], a3 = a3p[0];

    for (int tIdx = wid; tIdx < 64; tIdx += 32) {
        int h = tIdx >> 5, c = tIdx & 31;
        const float* gg = g_gram + ((size_t)(b * 2 + h)) * GRAM_STRIDE;
        float nq = fmaxf(sqrtf(gg[1024 + c]),    1e-12f);
        float nk = fmaxf(sqrtf(gg[1056 + lane]), 1e-12f);
        float val = gg[c * 32 + lane] * temperature[h] / (nq * nk);

        float sorted = warp_sort_desc(val, lane);
        float rowmax = __shfl_sync(0xffffffffu, sorted, 0);
        float t16 = __shfl_sync(0xffffffffu, sorted, 15);
        float t21 = __shfl_sync(0xffffffffu, sorted, 20);
        float t24 = __shfl_sync(0xffffffffu, sorted, 23);

        float w1 = topk_weight(val, t16, 16, lane, rowmax);
        float w2 = topk_weight(val, t21, 21, lane, rowmax);
        float w3 = topk_weight(val, t24, 24, lane, rowmax);
        A_s[h][c][lane] = a1 * w1 + a2 * w2 + a3 * w3;
    }
    __syncthreads();

    for (int idx = threadIdx.x; idx < 64 * 64; idx += 1024) {
        int o = idx >> 6, dg = idx & 63;
        int h = dg >> 5, d = dg & 31;
        float acc = 0.f;
#pragma unroll
        for (int j = 0; j < 32; j++)
            acc = fmaf(wproj[o * 64 + h * 32 + j], A_s[h][j][d], acc);
        g_M[(size_t)b * 4096 + o * 64 + dg] = acc;
    }
}

// ---------------------------------------------------------------------------
// K5: out[b,o,n] = sum_d M[b][o][d] * v_dw[b][d][n], FFMA2 micro-tile
// ---------------------------------------------------------------------------
__global__ __launch_bounds__(256) void k5_out(float* __restrict__ out) {
    __shared__ float xs[64][128];
    __shared__ float ws[64][64];
    int b  = blockIdx.z;
    int p0 = blockIdx.x * 128;

    const float* vb = g_qkvdw + ((size_t)b * QKV_CH + 128) * NPIX;
    for (int i = threadIdx.x; i < 64 * 32; i += 256) {
        int d = i >> 5, s = i & 31;
        *(float4*)&xs[d][s * 4] = *(const float4*)&vb[(size_t)d * NPIX + p0 + s * 4];
    }
    const float* Mb = g_M + (size_t)b * 4096;
    for (int i = threadIdx.x; i < 64 * 64; i += 256) {
        int d = i & 63, orow = i >> 6;
        ws[d][orow] = Mb[orow * 64 + d];
    }
    __syncthreads();

    int og = threadIdx.x >> 5, pg = threadIdx.x & 31;
    int ol0 = og * 8, pl0 = pg * 4;

    ull acc2[4][4];
#pragma unroll
    for (int o = 0; o < 4; o++)
#pragma unroll
        for (int p = 0; p < 4; p++) acc2[o][p] = 0ull;

#pragma unroll 8
    for (int d = 0; d < 64; d++) {
        ulonglong2 w01 = *(const ulonglong2*)&ws[d][ol0];
        ulonglong2 w23 = *(const ulonglong2*)&ws[d][ol0 + 4];
        float4 xv = *(const float4*)&xs[d][pl0];
        ull wp[4] = {w01.x, w01.y, w23.x, w23.y};
        ull xd[4] = {pack2(xv.x, xv.x), pack2(xv.y, xv.y),
                     pack2(xv.z, xv.z), pack2(xv.w, xv.w)};
#pragma unroll
        for (int o = 0; o < 4; o++)
#pragma unroll
            for (int p = 0; p < 4; p++)
                acc2[o][p] = ffma2(wp[o], xd[p], acc2[o][p]);
    }

    float* ob = out + (size_t)b * 64 * NPIX;
#pragma unroll
    for (int o = 0; o < 4; o++) {
        float2 u0 = unpack2(acc2[o][0]);
        float2 u1 = unpack2(acc2[o][1]);
        float2 u2 = unpack2(acc2[o][2]);
        float2 u3 = unpack2(acc2[o][3]);
        float4 rA = make_float4(u0.x, u1.x, u2.x, u3.x);
        float4 rB = make_float4(u0.y, u1.y, u2.y, u3.y);
        *(float4*)&ob[(size_t)(ol0 + 2 * o    ) * NPIX + p0 + pl0] = rA;
        *(float4*)&ob[(size_t)(ol0 + 2 * o + 1) * NPIX + p0 + pl0] = rB;
    }
}

// ---------------------------------------------------------------------------
extern "C" void kernel_launch(void* const* d_in, const int* in_sizes, int n_in,
                              void* d_out, int out_size) {
    const float* x     = (const float*)d_in[0];
    const float* wqkv  = (const float*)d_in[1];
    const float* wdw   = (const float*)d_in[2];
    const float* wproj = (const float*)d_in[3];
    const float* temp  = (const float*)d_in[4];
    const float* a1    = (const float*)d_in[5];
    const float* a2    = (const float*)d_in[6];
    const float* a3    = (const float*)d_in[7];
    float* out = (float*)d_out;

    k0_zero<<<(BATCH * 2 * GRAM_STRIDE + 255) / 256, 256>>>();

    dim3 g1(NPIX / 128, 3, BATCH);
    k1_qkv<<<g1, 256>>>(x, wqkv);

    dim3 g2(16, QKV_CH, BATCH);
    k2_dw<<<g2, 256>>>(wdw);

    dim3 g3(64, 2, BATCH);
    k3_gram<<<g3, 256>>>();

    k4_combine<<<BATCH, 1024>>>(wproj, temp, a1, a2, a3);

    dim3 g5(NPIX / 128, 1, BATCH);
    k5_out<<<g5, 256>>>(out);
}

// round 7
// speedup vs baseline: 1.5205x; 1.5205x over previous
#include <cuda_runtime.h>
#include <math.h>

#define NPIX (256*256)
#define BATCH 8
#define QKV_CH 192
#define GRAM_STRIDE 1088   // 32*32 Gqk + 32 qn2 + 32 kn2

typedef unsigned long long ull;

// Scratch (device globals — no allocation allowed). All fp32: the top-k
// selection is an order-statistic discontinuity; quantizing q/k flips
// selections and fails the 1e-3 gate (measured round 4: 1.1e-2).
__device__ float g_qkv  [(size_t)BATCH * QKV_CH * NPIX];
__device__ float g_qkvdw[(size_t)BATCH * QKV_CH * NPIX];
__device__ float g_gram [BATCH * 2 * GRAM_STRIDE];
__device__ float g_M    [BATCH * 64 * 64];

// ---------------------------------------------------------------------------
// f32x2 packed-FMA helpers (rn rounding == fmaf bit-exact per lane)
// ---------------------------------------------------------------------------
__device__ __forceinline__ ull pack2(float lo, float hi) {
    ull r; asm("mov.b64 %0, {%1, %2};" : "=l"(r) : "f"(lo), "f"(hi)); return r;
}
__device__ __forceinline__ ull ffma2(ull a, ull b, ull c) {
    ull d; asm("fma.rn.f32x2 %0, %1, %2, %3;" : "=l"(d) : "l"(a), "l"(b), "l"(c)); return d;
}
__device__ __forceinline__ float2 unpack2(ull v) {
    float2 f; asm("mov.b64 {%0, %1}, %2;" : "=f"(f.x), "=f"(f.y) : "l"(v)); return f;
}

// ---------------------------------------------------------------------------
// K0: zero gram accumulators (norms come from K2, gram from K3)
// ---------------------------------------------------------------------------
__global__ void k0_zero() {
    int i = blockIdx.x * 256 + threadIdx.x;
    if (i < BATCH * 2 * GRAM_STRIDE) g_gram[i] = 0.f;
}

// ---------------------------------------------------------------------------
// K1: qkv 1x1 conv == per-batch GEMM [192,64]x[64,N], FFMA2 micro-tile.
// ---------------------------------------------------------------------------
__global__ __launch_bounds__(256) void k1_qkv(const float* __restrict__ x,
                                              const float* __restrict__ wqkv) {
    __shared__ float xs[64][128];
    __shared__ float ws[64][64];
    int b  = blockIdx.z;
    int o0 = blockIdx.y * 64;
    int p0 = blockIdx.x * 128;

    const float* xb = x + (size_t)b * 64 * NPIX;
    for (int i = threadIdx.x; i < 64 * 32; i += 256) {
        int c = i >> 5, s = i & 31;
        *(float4*)&xs[c][s * 4] = *(const float4*)&xb[(size_t)c * NPIX + p0 + s * 4];
    }
    for (int i = threadIdx.x; i < 64 * 64; i += 256) {
        int c = i & 63, orow = i >> 6;
        ws[c][orow] = wqkv[(o0 + orow) * 64 + c];
    }
    __syncthreads();

    int og = threadIdx.x >> 5, pg = threadIdx.x & 31;
    int ol0 = og * 8, pl0 = pg * 4;

    ull acc2[4][4];
#pragma unroll
    for (int o = 0; o < 4; o++)
#pragma unroll
        for (int p = 0; p < 4; p++) acc2[o][p] = 0ull;

#pragma unroll 8
    for (int c = 0; c < 64; c++) {
        ulonglong2 w01 = *(const ulonglong2*)&ws[c][ol0];
        ulonglong2 w23 = *(const ulonglong2*)&ws[c][ol0 + 4];
        float4 xv = *(const float4*)&xs[c][pl0];
        ull wp[4] = {w01.x, w01.y, w23.x, w23.y};
        ull xd[4] = {pack2(xv.x, xv.x), pack2(xv.y, xv.y),
                     pack2(xv.z, xv.z), pack2(xv.w, xv.w)};
#pragma unroll
        for (int o = 0; o < 4; o++)
#pragma unroll
            for (int p = 0; p < 4; p++)
                acc2[o][p] = ffma2(wp[o], xd[p], acc2[o][p]);
    }

    float* outb = g_qkv + (size_t)b * QKV_CH * NPIX;
#pragma unroll
    for (int o = 0; o < 4; o++) {
        float2 u0 = unpack2(acc2[o][0]);
        float2 u1 = unpack2(acc2[o][1]);
        float2 u2 = unpack2(acc2[o][2]);
        float2 u3 = unpack2(acc2[o][3]);
        float4 rA = make_float4(u0.x, u1.x, u2.x, u3.x);
        float4 rB = make_float4(u0.y, u1.y, u2.y, u3.y);
        *(float4*)&outb[(size_t)(o0 + ol0 + 2 * o    ) * NPIX + p0 + pl0] = rA;
        *(float4*)&outb[(size_t)(o0 + ol0 + 2 * o + 1) * NPIX + p0 + pl0] = rB;
    }
}

// ---------------------------------------------------------------------------
// K2: depthwise 3x3, pad 1. 16 output rows/block, sliding 3-row register
// window. For ch<128 (q,k) also accumulate per-channel L2 norms into g_gram.
// ---------------------------------------------------------------------------
__global__ __launch_bounds__(256) void k2_dw(const float* __restrict__ wdw) {
    int b = blockIdx.z, ch = blockIdx.y, r0 = blockIdx.x * 16;
    __shared__ float rows[18][256];
    int tid = threadIdx.x;

    const float* in = g_qkv + ((size_t)(b * QKV_CH + ch)) * NPIX;
    for (int i = tid; i < 18 * 64; i += 256) {
        int row = i >> 6, seg = i & 63;
        int gr = r0 - 1 + row;
        float4 v = (gr >= 0 && gr < 256)
                 ? *(const float4*)(in + gr * 256 + seg * 4)
                 : make_float4(0.f, 0.f, 0.f, 0.f);
        *(float4*)&rows[row][seg * 4] = v;
    }
    __syncthreads();

    float w[9];
#pragma unroll
    for (int i = 0; i < 9; i++) w[i] = wdw[ch * 9 + i];

    int tx = tid;
    bool hasL = tx > 0, hasR = tx < 255;

    float vals[16];
    float l0, m0, r0v, l1, m1, r1v, l2, m2, r2v;
    m0 = rows[0][tx]; l0 = hasL ? rows[0][tx - 1] : 0.f; r0v = hasR ? rows[0][tx + 1] : 0.f;
    m1 = rows[1][tx]; l1 = hasL ? rows[1][tx - 1] : 0.f; r1v = hasR ? rows[1][tx + 1] : 0.f;
#pragma unroll
    for (int rr = 0; rr < 16; rr++) {
        m2 = rows[rr + 2][tx];
        l2 = hasL ? rows[rr + 2][tx - 1] : 0.f;
        r2v = hasR ? rows[rr + 2][tx + 1] : 0.f;
        float acc = 0.f;
        acc = fmaf(w[0], l0, acc); acc = fmaf(w[1], m0, acc); acc = fmaf(w[2], r0v, acc);
        acc = fmaf(w[3], l1, acc); acc = fmaf(w[4], m1, acc); acc = fmaf(w[5], r1v, acc);
        acc = fmaf(w[6], l2, acc); acc = fmaf(w[7], m2, acc); acc = fmaf(w[8], r2v, acc);
        vals[rr] = acc;
        l0 = l1; m0 = m1; r0v = r1v;
        l1 = l2; m1 = m2; r1v = r2v;
    }

    float* out = g_qkvdw + ((size_t)(b * QKV_CH + ch)) * NPIX;
#pragma unroll
    for (int rr = 0; rr < 16; rr++)
        out[(r0 + rr) * 256 + tx] = vals[rr];

    if (ch < 128) {
        float ss = 0.f;
#pragma unroll
        for (int rr = 0; rr < 16; rr++) ss = fmaf(vals[rr], vals[rr], ss);
#pragma unroll
        for (int o = 16; o; o >>= 1) ss += __shfl_xor_sync(0xffffffffu, ss, o);
        if ((tx & 31) == 0) {
            int h = (ch >> 5) & 1, c = ch & 31;
            float* gg = g_gram + ((size_t)(b * 2 + h)) * GRAM_STRIDE;
            atomicAdd(&gg[(ch < 64 ? 1024 : 1056) + c], ss);
        }
    }
}

// ---------------------------------------------------------------------------
// K3: Gram, software-pipelined. grid (32,2,8) = 512 blocks.
// 256 thr = 4 groups x 64 thr; group covers 512 px in 16 stages of 32 px.
// Stage s+1 globals are prefetched into registers while stage s computes,
// hiding DRAM latency behind the FFMA2 stream.
// ---------------------------------------------------------------------------
__global__ __launch_bounds__(256) void k3_gram() {
    int b = blockIdx.z, h = blockIdx.y, chunk = blockIdx.x;
    int g = threadIdx.x >> 6, t = threadIdx.x & 63;
    int tc = t >> 3, td = t & 7;
    __shared__ float qs[4][32][36];            // [group][px][ch]
    __shared__ float ks[4][32][36];
    size_t qbase = ((size_t)b * QKV_CH +      h * 32) * NPIX + chunk * 2048 + (size_t)g * 512;
    size_t kbase = ((size_t)b * QKV_CH + 64 + h * 32) * NPIX + chunk * 2048 + (size_t)g * 512;

    // Per-thread slot decode (constant across stages): 4 r-iters cover
    // 32 ch x 8 float4-px slots for q and k each.
    int chs[4], p4s[4];
#pragma unroll
    for (int r = 0; r < 4; r++) {
        int i = t + r * 64;
        chs[r] = i >> 3; p4s[r] = i & 7;
    }

    float4 pq[4], pk[4];
#pragma unroll
    for (int r = 0; r < 4; r++) {              // prefetch stage 0
        pq[r] = *(const float4*)&g_qkvdw[qbase + (size_t)chs[r] * NPIX + p4s[r] * 4];
        pk[r] = *(const float4*)&g_qkvdw[kbase + (size_t)chs[r] * NPIX + p4s[r] * 4];
    }

    ull acc2[4][2];
#pragma unroll
    for (int i = 0; i < 4; i++) { acc2[i][0] = 0ull; acc2[i][1] = 0ull; }

    for (int s = 0; s < 16; s++) {
        __syncthreads();                       // prior compute done reading smem
#pragma unroll
        for (int r = 0; r < 4; r++) {          // regs -> smem (transpose to [px][ch])
            int ch = chs[r], px = p4s[r] * 4;
            qs[g][px + 0][ch] = pq[r].x; qs[g][px + 1][ch] = pq[r].y;
            qs[g][px + 2][ch] = pq[r].z; qs[g][px + 3][ch] = pq[r].w;
            ks[g][px + 0][ch] = pk[r].x; ks[g][px + 1][ch] = pk[r].y;
            ks[g][px + 2][ch] = pk[r].z; ks[g][px + 3][ch] = pk[r].w;
        }
        __syncthreads();

        if (s + 1 < 16) {                      // prefetch next stage (overlaps compute)
            int off = (s + 1) * 32;
#pragma unroll
            for (int r = 0; r < 4; r++) {
                pq[r] = *(const float4*)&g_qkvdw[qbase + (size_t)chs[r] * NPIX + off + p4s[r] * 4];
                pk[r] = *(const float4*)&g_qkvdw[kbase + (size_t)chs[r] * NPIX + off + p4s[r] * 4];
            }
        }

#pragma unroll 4
        for (int p = 0; p < 32; p++) {
            float4 q4 = *(const float4*)&qs[g][p][tc * 4];
            ulonglong2 kp = *(const ulonglong2*)&ks[g][p][td * 4];
            ull qd;
            qd = pack2(q4.x, q4.x);
            acc2[0][0] = ffma2(qd, kp.x, acc2[0][0]);
            acc2[0][1] = ffma2(qd, kp.y, acc2[0][1]);
            qd = pack2(q4.y, q4.y);
            acc2[1][0] = ffma2(qd, kp.x, acc2[1][0]);
            acc2[1][1] = ffma2(qd, kp.y, acc2[1][1]);
            qd = pack2(q4.z, q4.z);
            acc2[2][0] = ffma2(qd, kp.x, acc2[2][0]);
            acc2[2][1] = ffma2(qd, kp.y, acc2[2][1]);
            qd = pack2(q4.w, q4.w);
            acc2[3][0] = ffma2(qd, kp.x, acc2[3][0]);
            acc2[3][1] = ffma2(qd, kp.y, acc2[3][1]);
        }
    }

    float* gg = g_gram + ((size_t)(b * 2 + h)) * GRAM_STRIDE;
#pragma unroll
    for (int i = 0; i < 4; i++) {
        int c = tc * 4 + i;
#pragma unroll
        for (int jp = 0; jp < 2; jp++) {
            float2 v = unpack2(acc2[i][jp]);
            atomicAdd(&gg[c * 32 + td * 4 + jp * 2 + 0], v.x);
            atomicAdd(&gg[c * 32 + td * 4 + jp * 2 + 1], v.y);
        }
    }
}

// ---------------------------------------------------------------------------
// K4: normalize attn, triple top-k softmax, fold Wproj -> M[64][64]
// ---------------------------------------------------------------------------
__device__ __forceinline__ float warp_sort_desc(float v, int lane) {
#pragma unroll
    for (int k = 2; k <= 32; k <<= 1) {
#pragma unroll
        for (int j = k >> 1; j > 0; j >>= 1) {
            float o = __shfl_xor_sync(0xffffffffu, v, j);
            bool up  = ((lane & k) == 0);
            bool low = ((lane & j) == 0);
            float mx = fmaxf(v, o), mn = fminf(v, o);
            v = (up == low) ? mx : mn;
        }
    }
    return v;
}

__device__ __forceinline__ float topk_weight(float orig, float thr, int kk,
                                             int lane, float rowmax) {
    unsigned full = 0xffffffffu;
    unsigned gt = __ballot_sync(full, orig > thr);
    int need = kk - __popc(gt);
    unsigned eq = __ballot_sync(full, orig == thr);
    unsigned lt_mask = (1u << lane) - 1u;
    bool incl = (orig > thr) ||
                ((orig == thr) && ((int)__popc(eq & lt_mask) < need));
    float e = incl ? expf(orig - rowmax) : 0.f;
    float s = e;
#pragma unroll
    for (int o = 16; o; o >>= 1) s += __shfl_xor_sync(full, s, o);
    return e / s;
}

__global__ __launch_bounds__(1024) void k4_combine(const float* __restrict__ wproj,
                                                   const float* __restrict__ temperature,
                                                   const float* __restrict__ a1p,
                                                   const float* __restrict__ a2p,
                                                   const float* __restrict__ a3p) {
    int b = blockIdx.x;
    int wid = threadIdx.x >> 5, lane = threadIdx.x & 31;
    __shared__ float A_s[2][32][32];
    float a1 = a1p[0], a2 = a2p[0], a3 = a3p[0];

    for (int tIdx = wid; tIdx < 64; tIdx += 32) {
        int h = tIdx >> 5, c = tIdx & 31;
        const float* gg = g_gram + ((size_t)(b * 2 + h)) * GRAM_STRIDE;
        float nq = fmaxf(sqrtf(gg[1024 + c]),    1e-12f);
        float nk = fmaxf(sqrtf(gg[1056 + lane]), 1e-12f);
        float val = gg[c * 32 + lane] * temperature[h] / (nq * nk);

        float sorted = warp_sort_desc(val, lane);
        float rowmax = __shfl_sync(0xffffffffu, sorted, 0);
        float t16 = __shfl_sync(0xffffffffu, sorted, 15);
        float t21 = __shfl_sync(0xffffffffu, sorted, 20);
        float t24 = __shfl_sync(0xffffffffu, sorted, 23);

        float w1 = topk_weight(val, t16, 16, lane, rowmax);
        float w2 = topk_weight(val, t21, 21, lane, rowmax);
        float w3 = topk_weight(val, t24, 24, lane, rowmax);
        A_s[h][c][lane] = a1 * w1 + a2 * w2 + a3 * w3;
    }
    __syncthreads();

    for (int idx = threadIdx.x; idx < 64 * 64; idx += 1024) {
        int o = idx >> 6, dg = idx & 63;
        int h = dg >> 5, d = dg & 31;
        float acc = 0.f;
#pragma unroll
        for (int j = 0; j < 32; j++)
            acc = fmaf(wproj[o * 64 + h * 32 + j], A_s[h][j][d], acc);
        g_M[(size_t)b * 4096 + o * 64 + dg] = acc;
    }
}

// ---------------------------------------------------------------------------
// K5: out[b,o,n] = sum_d M[b][o][d] * v_dw[b][d][n], FFMA2 micro-tile
// ---------------------------------------------------------------------------
__global__ __launch_bounds__(256) void k5_out(float* __restrict__ out) {
    __shared__ float xs[64][128];
    __shared__ float ws[64][64];
    int b  = blockIdx.z;
    int p0 = blockIdx.x * 128;

    const float* vb = g_qkvdw + ((size_t)b * QKV_CH + 128) * NPIX;
    for (int i = threadIdx.x; i < 64 * 32; i += 256) {
        int d = i >> 5, s = i & 31;
        *(float4*)&xs[d][s * 4] = *(const float4*)&vb[(size_t)d * NPIX + p0 + s * 4];
    }
    const float* Mb = g_M + (size_t)b * 4096;
    for (int i = threadIdx.x; i < 64 * 64; i += 256) {
        int d = i & 63, orow = i >> 6;
        ws[d][orow] = Mb[orow * 64 + d];
    }
    __syncthreads();

    int og = threadIdx.x >> 5, pg = threadIdx.x & 31;
    int ol0 = og * 8, pl0 = pg * 4;

    ull acc2[4][4];
#pragma unroll
    for (int o = 0; o < 4; o++)
#pragma unroll
        for (int p = 0; p < 4; p++) acc2[o][p] = 0ull;

#pragma unroll 8
    for (int d = 0; d < 64; d++) {
        ulonglong2 w01 = *(const ulonglong2*)&ws[d][ol0];
        ulonglong2 w23 = *(const ulonglong2*)&ws[d][ol0 + 4];
        float4 xv = *(const float4*)&xs[d][pl0];
        ull wp[4] = {w01.x, w01.y, w23.x, w23.y};
        ull xd[4] = {pack2(xv.x, xv.x), pack2(xv.y, xv.y),
                     pack2(xv.z, xv.z), pack2(xv.w, xv.w)};
#pragma unroll
        for (int o = 0; o < 4; o++)
#pragma unroll
            for (int p = 0; p < 4; p++)
                acc2[o][p] = ffma2(wp[o], xd[p], acc2[o][p]);
    }

    float* ob = out + (size_t)b * 64 * NPIX;
#pragma unroll
    for (int o = 0; o < 4; o++) {
        float2 u0 = unpack2(acc2[o][0]);
        float2 u1 = unpack2(acc2[o][1]);
        float2 u2 = unpack2(acc2[o][2]);
        float2 u3 = unpack2(acc2[o][3]);
        float4 rA = make_float4(u0.x, u1.x, u2.x, u3.x);
        float4 rB = make_float4(u0.y, u1.y, u2.y, u3.y);
        *(float4*)&ob[(size_t)(ol0 + 2 * o    ) * NPIX + p0 + pl0] = rA;
        *(float4*)&ob[(size_t)(ol0 + 2 * o + 1) * NPIX + p0 + pl0] = rB;
    }
}

// ---------------------------------------------------------------------------
extern "C" void kernel_launch(void* const* d_in, const int* in_sizes, int n_in,
                              void* d_out, int out_size) {
    const float* x     = (const float*)d_in[0];
    const float* wqkv  = (const float*)d_in[1];
    const float* wdw   = (const float*)d_in[2];
    const float* wproj = (const float*)d_in[3];
    const float* temp  = (const float*)d_in[4];
    const float* a1    = (const float*)d_in[5];
    const float* a2    = (const float*)d_in[6];
    const float* a3    = (const float*)d_in[7];
    float* out = (float*)d_out;

    k0_zero<<<(BATCH * 2 * GRAM_STRIDE + 255) / 256, 256>>>();

    dim3 g1(NPIX / 128, 3, BATCH);
    k1_qkv<<<g1, 256>>>(x, wqkv);

    dim3 g2(16, QKV_CH, BATCH);
    k2_dw<<<g2, 256>>>(wdw);

    dim3 g3(32, 2, BATCH);
    k3_gram<<<g3, 256>>>();

    k4_combine<<<BATCH, 1024>>>(wproj, temp, a1, a2, a3);

    dim3 g5(NPIX / 128, 1, BATCH);
    k5_out<<<g5, 256>>>(out);
}